// round 9
// baseline (speedup 1.0000x reference)
#include <cuda_runtime.h>
#include <cuda_bf16.h>
#include <cuda_fp16.h>
#include <math.h>
#include <cstdint>

#define TOTE (4096 * 768)
#define WELE (768 * 768)
#define AST 72     // bf16 smem row stride for 64-wide tiles (144B)
#define BST 40     // bf16 smem row stride for 32-wide K-chunks (80B)
#define WSTW 36    // W fp32 smem row stride (144B)

// Scratch (allocation-free rule: __device__ globals)
__device__ __nv_bfloat16 g_ahi[TOTE];        // activation split (query, then att out)
__device__ __nv_bfloat16 g_alo[TOTE];
__device__ __nv_bfloat16 g_whi[4 * WELE];    // Wq|Wk|Wv|Wo hi
__device__ __nv_bfloat16 g_wlo[4 * WELE];
__device__ __nv_bfloat16 g_qkh[2 * TOTE];    // Q|K hi
__device__ __nv_bfloat16 g_qkl[2 * TOTE];    // Q|K lo
__device__ __half        g_vf[TOTE];         // V fp16

// ===========================================================================
// Base-sm_103-safe helpers (no tcgen05: ptxas virtual target is compute_103)
// ===========================================================================
__device__ __forceinline__ uint32_t smem_u32(const void* p) {
    uint32_t a;
    asm("{ .reg .u64 t; cvta.to.shared.u64 t, %1; cvt.u32.u64 %0, t; }" : "=r"(a) : "l"(p));
    return a;
}
__device__ __forceinline__ void ldsm_x4(uint32_t* r, uint32_t addr) {
    asm volatile("ldmatrix.sync.aligned.m8n8.x4.shared.b16 {%0,%1,%2,%3}, [%4];"
                 : "=r"(r[0]), "=r"(r[1]), "=r"(r[2]), "=r"(r[3]) : "r"(addr));
}
__device__ __forceinline__ void ldsm_x4_t(uint32_t* r, uint32_t addr) {
    asm volatile("ldmatrix.sync.aligned.m8n8.x4.trans.shared.b16 {%0,%1,%2,%3}, [%4];"
                 : "=r"(r[0]), "=r"(r[1]), "=r"(r[2]), "=r"(r[3]) : "r"(addr));
}
__device__ __forceinline__ void mma_bf(float* d, const uint32_t* a, uint32_t b0, uint32_t b1) {
    asm volatile(
        "mma.sync.aligned.m16n8k16.row.col.f32.bf16.bf16.f32 "
        "{%0,%1,%2,%3}, {%4,%5,%6,%7}, {%8,%9}, {%0,%1,%2,%3};"
        : "+f"(d[0]), "+f"(d[1]), "+f"(d[2]), "+f"(d[3])
        : "r"(a[0]), "r"(a[1]), "r"(a[2]), "r"(a[3]), "r"(b0), "r"(b1));
}
__device__ __forceinline__ void mma_f16(float* d, const uint32_t* a, uint32_t b0, uint32_t b1) {
    asm volatile(
        "mma.sync.aligned.m16n8k16.row.col.f32.f16.f16.f32 "
        "{%0,%1,%2,%3}, {%4,%5,%6,%7}, {%8,%9}, {%0,%1,%2,%3};"
        : "+f"(d[0]), "+f"(d[1]), "+f"(d[2]), "+f"(d[3])
        : "r"(a[0]), "r"(a[1]), "r"(a[2]), "r"(a[3]), "r"(b0), "r"(b1));
}
__device__ __forceinline__ uint32_t pack_f16x2(float lo, float hi) {
    uint32_t d;
    asm("cvt.rn.f16x2.f32 %0, %1, %2;" : "=r"(d) : "f"(hi), "f"(lo));
    return d;
}
__device__ __forceinline__ void cpa16(uint32_t dst, const void* src) {
    asm volatile("cp.async.cg.shared.global [%0], [%1], 16;" :: "r"(dst), "l"(src) : "memory");
}

// ===========================================================================
// fp32 -> bf16 hi/lo splits
// ===========================================================================
__global__ __launch_bounds__(256) void split_f32(
    const float4* __restrict__ x, uint2* __restrict__ hi, uint2* __restrict__ lo, int n4)
{
    int i = blockIdx.x * blockDim.x + threadIdx.x;
    if (i >= n4) return;
    float4 v = x[i];
    float vv[4] = {v.x, v.y, v.z, v.w};
    __nv_bfloat16 h[4], l[4];
#pragma unroll
    for (int j = 0; j < 4; j++) {
        h[j] = __float2bfloat16(vv[j]);
        l[j] = __float2bfloat16(vv[j] - __bfloat162float(h[j]));
    }
    hi[i] = *(uint2*)h;
    lo[i] = *(uint2*)l;
}

__global__ __launch_bounds__(256) void split_w(
    const float4* __restrict__ w0, const float4* __restrict__ w1,
    const float4* __restrict__ w2, const float4* __restrict__ w3,
    uint2* __restrict__ hi, uint2* __restrict__ lo)
{
    const int z = blockIdx.y;
    const float4* src = (z == 0) ? w0 : (z == 1) ? w1 : (z == 2) ? w2 : w3;
    int i = blockIdx.x * blockDim.x + threadIdx.x;
    if (i >= WELE / 4) return;
    float4 v = src[i];
    float vv[4] = {v.x, v.y, v.z, v.w};
    __nv_bfloat16 h[4], l[4];
#pragma unroll
    for (int j = 0; j < 4; j++) {
        h[j] = __float2bfloat16(vv[j]);
        l[j] = __float2bfloat16(vv[j] - __bfloat162float(h[j]));
    }
    hi[(size_t)z * (WELE / 4) + i] = *(uint2*)h;
    lo[(size_t)z * (WELE / 4) + i] = *(uint2*)l;
}

// ===========================================================================
// HMMA split-bf16 NT GEMM, 4-stage cp.async pipeline, K-chunk 32.
// ===========================================================================
#define GTILEB (128 * BST * 2)       // 10240 B per array per stage
#define GSTB   (4 * GTILEB)          // stage stride 40960 B

__global__ __launch_bounds__(256) void gemm_mma(
    const __nv_bfloat16* __restrict__ Ahi, const __nv_bfloat16* __restrict__ Alo,
    const __nv_bfloat16* __restrict__ Whi, const __nv_bfloat16* __restrict__ Wlo,
    const float* __restrict__ bias, float* __restrict__ Cf,
    __nv_bfloat16* __restrict__ Chi, __nv_bfloat16* __restrict__ Clo,
    __half* __restrict__ Cf16, int wbase)
{
    extern __shared__ __align__(16) __nv_bfloat16 smb[];
    const uint32_t sb = smem_u32(smb);

    const int tid = threadIdx.x, wid = tid >> 5, lane = tid & 31;
    const int wm = (wid >> 1) * 32, wn = (wid & 1) * 64;
    const int m0 = blockIdx.y * 128, n0 = blockIdx.x * 128;
    const int z = blockIdx.z;

    const __nv_bfloat16* gAh = Ahi + (size_t)m0 * 768;
    const __nv_bfloat16* gAl = Alo + (size_t)m0 * 768;
    const __nv_bfloat16* gBh = Whi + (size_t)(wbase + z) * WELE + (size_t)n0 * 768;
    const __nv_bfloat16* gBl = Wlo + (size_t)(wbase + z) * WELE + (size_t)n0 * 768;

    float acc[2][8][4];
#pragma unroll
    for (int i = 0; i < 2; i++)
#pragma unroll
        for (int j = 0; j < 8; j++)
#pragma unroll
            for (int k = 0; k < 4; k++) acc[i][j][k] = 0.f;

#define GSTAGE(buf, c_)                                                        \
    {                                                                          \
        uint32_t base_ = sb + (buf) * GSTB;                                    \
        const int k0_ = (c_) * 32;                                             \
        _Pragma("unroll")                                                      \
        for (int it = 0; it < 2; it++) {                                       \
            int idx = it * 256 + tid;                                          \
            int row = idx >> 2, cc = idx & 3;                                  \
            uint32_t off = (uint32_t)(row * BST + cc * 8) * 2;                 \
            size_t go = (size_t)row * 768 + k0_ + cc * 8;                      \
            cpa16(base_ + off,              gAh + go);                         \
            cpa16(base_ + GTILEB + off,     gAl + go);                         \
            cpa16(base_ + 2 * GTILEB + off, gBh + go);                         \
            cpa16(base_ + 3 * GTILEB + off, gBl + go);                         \
        }                                                                      \
        asm volatile("cp.async.commit_group;" ::: "memory");                   \
    }

    GSTAGE(0, 0); GSTAGE(1, 1); GSTAGE(2, 2);

    const int lrow = lane & 15, lcol8 = (lane >> 4) * 8;
    const uint32_t offA = (uint32_t)((wm + lrow) * BST + lcol8) * 2;
    const uint32_t offB = (uint32_t)((wn + lrow) * BST + lcol8) * 2;

    for (int c = 0; c < 24; c++) {
        if (c + 3 < 24) {
            GSTAGE((c + 3) & 3, c + 3);
            asm volatile("cp.async.wait_group 3;" ::: "memory");
        } else {
            asm volatile("cp.async.wait_group 0;" ::: "memory");
        }
        __syncthreads();
        uint32_t base = sb + (c & 3) * GSTB;
        uint32_t aAh = base + offA, aAl = base + GTILEB + offA;
        uint32_t aBh = base + 2 * GTILEB + offB, aBl = base + 3 * GTILEB + offB;
#pragma unroll
        for (int kk = 0; kk < 2; kk++) {
            const uint32_t koff = kk * 32;   // 16 elements * 2B
            uint32_t ah[2][4], al[2][4], bh[4][4], bl[4][4];
#pragma unroll
            for (int mf = 0; mf < 2; mf++) {
                ldsm_x4(ah[mf], aAh + mf * 16 * BST * 2 + koff);
                ldsm_x4(al[mf], aAl + mf * 16 * BST * 2 + koff);
            }
#pragma unroll
            for (int nq = 0; nq < 4; nq++) {
                ldsm_x4(bh[nq], aBh + nq * 16 * BST * 2 + koff);
                ldsm_x4(bl[nq], aBl + nq * 16 * BST * 2 + koff);
            }
#pragma unroll
            for (int mf = 0; mf < 2; mf++) {
#pragma unroll
                for (int nq = 0; nq < 4; nq++) {
                    float* a0 = acc[mf][nq * 2 + 0];
                    float* a1 = acc[mf][nq * 2 + 1];
                    mma_bf(a0, ah[mf], bh[nq][0], bh[nq][2]);
                    mma_bf(a1, ah[mf], bh[nq][1], bh[nq][3]);
                    mma_bf(a0, al[mf], bh[nq][0], bh[nq][2]);
                    mma_bf(a1, al[mf], bh[nq][1], bh[nq][3]);
                    mma_bf(a0, ah[mf], bl[nq][0], bl[nq][2]);
                    mma_bf(a1, ah[mf], bl[nq][1], bl[nq][3]);
                }
            }
        }
        __syncthreads();
    }

#pragma unroll
    for (int mf = 0; mf < 2; mf++) {
#pragma unroll
        for (int nf = 0; nf < 8; nf++) {
            int row = m0 + wm + mf * 16 + (lane >> 2);
            int col = n0 + wn + nf * 8 + (lane & 3) * 2;
            float v0 = acc[mf][nf][0], v1 = acc[mf][nf][1];
            float v2 = acc[mf][nf][2], v3 = acc[mf][nf][3];
            if (Cf) {
                float b0 = bias[col], b1 = bias[col + 1];
                *(float2*)(Cf + (size_t)row * 768 + col) = make_float2(v0 + b0, v1 + b1);
                *(float2*)(Cf + (size_t)(row + 8) * 768 + col) = make_float2(v2 + b0, v3 + b1);
            } else if (z == 2) {
                __half2 h0 = __floats2half2_rn(v0, v1);
                __half2 h1 = __floats2half2_rn(v2, v3);
                *(uint32_t*)(Cf16 + (size_t)row * 768 + col) = *(uint32_t*)&h0;
                *(uint32_t*)(Cf16 + (size_t)(row + 8) * 768 + col) = *(uint32_t*)&h1;
            } else {
                __nv_bfloat16* ch = Chi + (size_t)z * TOTE;
                __nv_bfloat16* cl = Clo + (size_t)z * TOTE;
                __nv_bfloat16 h0 = __float2bfloat16(v0), h1 = __float2bfloat16(v1);
                __nv_bfloat16 h2 = __float2bfloat16(v2), h3 = __float2bfloat16(v3);
                __nv_bfloat162 ph0 = {h0, h1}, ph1 = {h2, h3};
                __nv_bfloat162 pl0 = {__float2bfloat16(v0 - __bfloat162float(h0)),
                                      __float2bfloat16(v1 - __bfloat162float(h1))};
                __nv_bfloat162 pl1 = {__float2bfloat16(v2 - __bfloat162float(h2)),
                                      __float2bfloat16(v3 - __bfloat162float(h3))};
                *(uint32_t*)(ch + (size_t)row * 768 + col) = *(uint32_t*)&ph0;
                *(uint32_t*)(ch + (size_t)(row + 8) * 768 + col) = *(uint32_t*)&ph1;
                *(uint32_t*)(cl + (size_t)row * 768 + col) = *(uint32_t*)&pl0;
                *(uint32_t*)(cl + (size_t)(row + 8) * 768 + col) = *(uint32_t*)&pl1;
            }
        }
    }
}

// ===========================================================================
// HMMA fused biased flash attention, v3: key tile 32, 3-stage cp.async
// pipeline (K hi/lo + V + W), 2 CTAs/SM.
// ===========================================================================
#define KT 32
#define KVB (KT * AST * 2)            // 4608 B per K/V array per stage
#define WB  (128 * WSTW * 4)          // 18432 B W tile per stage
#define STB (3 * KVB + WB)            // stage stride 32256 B

__global__ __launch_bounds__(256, 2) void attn_mma(
    const __nv_bfloat16* __restrict__ qkh, const __nv_bfloat16* __restrict__ qkl,
    const __half* __restrict__ vf, const float* __restrict__ W,
    __nv_bfloat16* __restrict__ ohi, __nv_bfloat16* __restrict__ olo)
{
    extern __shared__ __align__(16) char smn[];
    const uint32_t sb = smem_u32(smn);

    const int tid = threadIdx.x, wp = tid >> 5, lane = tid & 31;
    const int n0 = blockIdx.x * 128, h = blockIdx.y, b = blockIdx.z;

    const __nv_bfloat16* qh = qkh + ((size_t)(b * 1024 + n0)) * 768 + h * 64;
    const __nv_bfloat16* ql = qkl + ((size_t)(b * 1024 + n0)) * 768 + h * 64;
    const __nv_bfloat16* kh = qkh + (size_t)TOTE + (size_t)b * 1024 * 768 + h * 64;
    const __nv_bfloat16* kl = qkl + (size_t)TOTE + (size_t)b * 1024 * 768 + h * 64;
    const __half* vg = vf + (size_t)b * 1024 * 768 + h * 64;
    const float* wg = W + ((size_t)(b * 12 + h) * 1024 + n0) * 1024;

    // --- Stage Q (128x64) hi/lo through smem (pre-pipeline), frags to regs ---
    {
        __nv_bfloat16* tQh = (__nv_bfloat16*)smn;
        __nv_bfloat16* tQl = tQh + 128 * AST;
#pragma unroll
        for (int it = 0; it < 4; it++) {
            int idx = it * 256 + tid;
            int row = idx >> 3, cc = idx & 7;
            *(uint4*)(tQh + row * AST + cc * 8) = *(const uint4*)(qh + (size_t)row * 768 + cc * 8);
            *(uint4*)(tQl + row * AST + cc * 8) = *(const uint4*)(ql + (size_t)row * 768 + cc * 8);
        }
    }
    __syncthreads();
    uint32_t qfh[4][4], qfl[4][4];
    {
        uint32_t off = (uint32_t)((wp * 16 + (lane & 15)) * AST + (lane >> 4) * 8) * 2;
#pragma unroll
        for (int ks = 0; ks < 4; ks++) {
            ldsm_x4(qfh[ks], sb + off + ks * 32);
            ldsm_x4(qfl[ks], sb + 128 * AST * 2 + off + ks * 32);
        }
    }
    __syncthreads();

    float oacc[8][4];
#pragma unroll
    for (int d = 0; d < 8; d++)
#pragma unroll
        for (int j = 0; j < 4; j++) oacc[d][j] = 0.f;
    float m0r = -INFINITY, m1r = -INFINITY, l0r = 0.f, l1r = 0.f;

#define ASTAGE(buf, t_)                                                        \
    {                                                                          \
        uint32_t base_ = sb + (buf) * STB;                                     \
        const int s0_ = (t_) * KT;                                             \
        {                                                                      \
            int row = tid >> 3, cc = tid & 7;                                  \
            uint32_t doff = (uint32_t)(row * AST + cc * 8) * 2;                \
            size_t go = (size_t)(s0_ + row) * 768 + cc * 8;                    \
            cpa16(base_ + doff,           kh + go);                            \
            cpa16(base_ + KVB + doff,     kl + go);                            \
            cpa16(base_ + 2 * KVB + doff, vg + go);                            \
        }                                                                      \
        _Pragma("unroll")                                                      \
        for (int it = 0; it < 4; it++) {                                       \
            int idx = it * 256 + tid;                                          \
            int row = idx >> 3, cc = idx & 7;                                  \
            cpa16(base_ + 3 * KVB + (uint32_t)(row * WSTW + cc * 4) * 4,       \
                  wg + (size_t)row * 1024 + s0_ + cc * 4);                     \
        }                                                                      \
        asm volatile("cp.async.commit_group;" ::: "memory");                   \
    }

    ASTAGE(0, 0); ASTAGE(1, 1);

    const uint32_t foff = (uint32_t)(((lane & 15) * AST) + (lane >> 4) * 8) * 2;
    const int c0 = (lane & 3) * 2;
    const uint32_t woff = (uint32_t)((wp * 16 + (lane >> 2)) * WSTW + c0) * 4;

    for (int t = 0; t < 32; t++) {
        if (t + 2 < 32) {
            ASTAGE((t + 2) % 3, t + 2);
            asm volatile("cp.async.wait_group 2;" ::: "memory");
        } else {
            asm volatile("cp.async.wait_group 0;" ::: "memory");
        }
        __syncthreads();
        uint32_t base = sb + (t % 3) * STB;
        uint32_t kbh = base + foff, kbl = base + KVB + foff;
        uint32_t vbb = base + 2 * KVB + foff;
        uint32_t wb0 = base + 3 * KVB + woff;

        // ---- S = Q K^T (3-term split-bf16), 32 keys ----
        float sc[4][4];
#pragma unroll
        for (int nf = 0; nf < 4; nf++)
#pragma unroll
            for (int j = 0; j < 4; j++) sc[nf][j] = 0.f;
#pragma unroll
        for (int nf2 = 0; nf2 < 2; nf2++) {
#pragma unroll
            for (int ks = 0; ks < 4; ks++) {
                uint32_t off = (uint32_t)(nf2 * 16 * AST + ks * 16) * 2;
                uint32_t fh[4], fl[4];
                ldsm_x4(fh, kbh + off);
                ldsm_x4(fl, kbl + off);
                mma_bf(sc[2 * nf2],     qfh[ks], fh[0], fh[2]);
                mma_bf(sc[2 * nf2 + 1], qfh[ks], fh[1], fh[3]);
                mma_bf(sc[2 * nf2],     qfl[ks], fh[0], fh[2]);
                mma_bf(sc[2 * nf2 + 1], qfl[ks], fh[1], fh[3]);
                mma_bf(sc[2 * nf2],     qfh[ks], fl[0], fl[2]);
                mma_bf(sc[2 * nf2 + 1], qfh[ks], fl[1], fl[3]);
            }
        }

        // ---- bias (from smem) + online softmax ----
        float nm0 = m0r, nm1 = m1r;
#pragma unroll
        for (int nf = 0; nf < 4; nf++) {
            float2 w0, w1;
            asm volatile("ld.shared.v2.f32 {%0,%1}, [%2];"
                         : "=f"(w0.x), "=f"(w0.y) : "r"(wb0 + nf * 32));
            asm volatile("ld.shared.v2.f32 {%0,%1}, [%2];"
                         : "=f"(w1.x), "=f"(w1.y) : "r"(wb0 + 8 * WSTW * 4 + nf * 32));
            sc[nf][0] = fmaf(sc[nf][0], 0.125f, w0.x);
            sc[nf][1] = fmaf(sc[nf][1], 0.125f, w0.y);
            sc[nf][2] = fmaf(sc[nf][2], 0.125f, w1.x);
            sc[nf][3] = fmaf(sc[nf][3], 0.125f, w1.y);
            nm0 = fmaxf(nm0, fmaxf(sc[nf][0], sc[nf][1]));
            nm1 = fmaxf(nm1, fmaxf(sc[nf][2], sc[nf][3]));
        }
        nm0 = fmaxf(nm0, __shfl_xor_sync(0xffffffffu, nm0, 1));
        nm0 = fmaxf(nm0, __shfl_xor_sync(0xffffffffu, nm0, 2));
        nm1 = fmaxf(nm1, __shfl_xor_sync(0xffffffffu, nm1, 1));
        nm1 = fmaxf(nm1, __shfl_xor_sync(0xffffffffu, nm1, 2));
        float corr0 = __expf(m0r - nm0), corr1 = __expf(m1r - nm1);
        m0r = nm0; m1r = nm1;
        float rs0 = 0.f, rs1 = 0.f;
#pragma unroll
        for (int nf = 0; nf < 4; nf++) {
            sc[nf][0] = __expf(sc[nf][0] - nm0);
            sc[nf][1] = __expf(sc[nf][1] - nm0);
            sc[nf][2] = __expf(sc[nf][2] - nm1);
            sc[nf][3] = __expf(sc[nf][3] - nm1);
            rs0 += sc[nf][0] + sc[nf][1];
            rs1 += sc[nf][2] + sc[nf][3];
        }
        l0r = l0r * corr0 + rs0;
        l1r = l1r * corr1 + rs1;
#pragma unroll
        for (int d = 0; d < 8; d++) {
            oacc[d][0] *= corr0; oacc[d][1] *= corr0;
            oacc[d][2] *= corr1; oacc[d][3] *= corr1;
        }

        // ---- out += P V (fp16, P from registers) ----
#pragma unroll
        for (int kc = 0; kc < 2; kc++) {
            uint32_t pa[4];
            pa[0] = pack_f16x2(sc[2 * kc][0], sc[2 * kc][1]);
            pa[1] = pack_f16x2(sc[2 * kc][2], sc[2 * kc][3]);
            pa[2] = pack_f16x2(sc[2 * kc + 1][0], sc[2 * kc + 1][1]);
            pa[3] = pack_f16x2(sc[2 * kc + 1][2], sc[2 * kc + 1][3]);
#pragma unroll
            for (int dp = 0; dp < 4; dp++) {
                uint32_t vf4[4];
                ldsm_x4_t(vf4, vbb + (uint32_t)(kc * 16 * AST + dp * 16) * 2);
                mma_f16(oacc[2 * dp],     pa, vf4[0], vf4[1]);
                mma_f16(oacc[2 * dp + 1], pa, vf4[2], vf4[3]);
            }
        }
        __syncthreads();
    }

    // ---- normalize + write bf16 hi/lo (att layout [4096, 768]) ----
    l0r += __shfl_xor_sync(0xffffffffu, l0r, 1);
    l0r += __shfl_xor_sync(0xffffffffu, l0r, 2);
    l1r += __shfl_xor_sync(0xffffffffu, l1r, 1);
    l1r += __shfl_xor_sync(0xffffffffu, l1r, 2);
    float i0 = 1.f / l0r, i1 = 1.f / l1r;
    int row = b * 1024 + n0 + wp * 16 + (lane >> 2);
    int colb = h * 64 + c0;
#pragma unroll
    for (int d = 0; d < 8; d++) {
        float v0 = oacc[d][0] * i0, v1 = oacc[d][1] * i0;
        float v2 = oacc[d][2] * i1, v3 = oacc[d][3] * i1;
        __nv_bfloat16 h0 = __float2bfloat16(v0), h1 = __float2bfloat16(v1);
        __nv_bfloat16 h2 = __float2bfloat16(v2), h3 = __float2bfloat16(v3);
        __nv_bfloat162 ph0 = {h0, h1}, ph1 = {h2, h3};
        __nv_bfloat162 pl0 = {__float2bfloat16(v0 - __bfloat162float(h0)),
                              __float2bfloat16(v1 - __bfloat162float(h1))};
        __nv_bfloat162 pl1 = {__float2bfloat16(v2 - __bfloat162float(h2)),
                              __float2bfloat16(v3 - __bfloat162float(h3))};
        *(uint32_t*)(ohi + (size_t)row * 768 + colb + d * 8) = *(uint32_t*)&ph0;
        *(uint32_t*)(ohi + (size_t)(row + 8) * 768 + colb + d * 8) = *(uint32_t*)&ph1;
        *(uint32_t*)(olo + (size_t)row * 768 + colb + d * 8) = *(uint32_t*)&pl0;
        *(uint32_t*)(olo + (size_t)(row + 8) * 768 + colb + d * 8) = *(uint32_t*)&pl1;
    }
}

// ===========================================================================
// Launch
// ===========================================================================
extern "C" void kernel_launch(void* const* d_in, const int* in_sizes, int n_in,
                              void* d_out, int out_size)
{
    const float* query = (const float*)d_in[0];
    const float* attw  = (const float*)d_in[1];
    const float* Wq    = (const float*)d_in[2];
    const float* Wk    = (const float*)d_in[3];
    const float* Wv    = (const float*)d_in[4];
    const float* Wo    = (const float*)d_in[5];
    const float* bo    = (const float*)d_in[6];
    float* out = (float*)d_out;

    __nv_bfloat16 *ahi, *alo, *whi, *wlo, *qkh, *qkl;
    __half* vfp;
    cudaGetSymbolAddress((void**)&ahi, g_ahi);
    cudaGetSymbolAddress((void**)&alo, g_alo);
    cudaGetSymbolAddress((void**)&whi, g_whi);
    cudaGetSymbolAddress((void**)&wlo, g_wlo);
    cudaGetSymbolAddress((void**)&qkh, g_qkh);
    cudaGetSymbolAddress((void**)&qkl, g_qkl);
    cudaGetSymbolAddress((void**)&vfp, g_vf);

    const int gemm_smem = 4 * GSTB;                // 163840
    cudaFuncSetAttribute(gemm_mma, cudaFuncAttributeMaxDynamicSharedMemorySize, gemm_smem);
    const int attn_smem = 3 * STB;                 // 96768 (2 CTAs/SM)
    cudaFuncSetAttribute(attn_mma, cudaFuncAttributeMaxDynamicSharedMemorySize, attn_smem);

    // 1) Split query + all four weights
    split_f32<<<TOTE / 4 / 256, 256>>>((const float4*)query, (uint2*)ahi, (uint2*)alo, TOTE / 4);
    split_w<<<dim3(WELE / 4 / 256, 4), 256>>>((const float4*)Wq, (const float4*)Wk,
                                              (const float4*)Wv, (const float4*)Wo,
                                              (uint2*)whi, (uint2*)wlo);

    // 2) QKV: z<2 -> Q/K bf16 hi/lo, z==2 -> V fp16
    gemm_mma<<<dim3(6, 32, 3), 256, gemm_smem>>>(ahi, alo, whi, wlo,
                                                 nullptr, nullptr, qkh, qkl, vfp, 0);

    // 3) Fused biased attention; att hi/lo -> ahi/alo
    attn_mma<<<dim3(8, 12, 4), 256, attn_smem>>>(qkh, qkl, vfp, attw, ahi, alo);

    // 4) Output projection (fp32 + bias)
    gemm_mma<<<dim3(6, 32, 1), 256, gemm_smem>>>(ahi, alo, whi, wlo,
                                                 bo, out, nullptr, nullptr, nullptr, 3);
}

// round 10
// speedup vs baseline: 1.1405x; 1.1405x over previous
#include <cuda_runtime.h>
#include <cuda_bf16.h>
#include <cuda_fp16.h>
#include <math.h>
#include <cstdint>

#define TOTE (4096 * 768)
#define WELE (768 * 768)
#define AST 72     // bf16 smem row stride for 64-wide tiles (144B)
#define WSTW 36    // W fp32 smem row stride (144B)

// Scratch (allocation-free rule: __device__ globals)
__device__ __nv_bfloat16 g_ahi[TOTE];        // activation split (query, then att out)
__device__ __nv_bfloat16 g_alo[TOTE];
__device__ __nv_bfloat16 g_whi[4 * WELE];    // Wq|Wk|Wv|Wo hi
__device__ __nv_bfloat16 g_wlo[4 * WELE];
__device__ __nv_bfloat16 g_qkh[2 * TOTE];    // Q|K hi
__device__ __nv_bfloat16 g_qkl[2 * TOTE];    // Q|K lo
__device__ __half        g_vf[TOTE];         // V fp16

// ===========================================================================
// Base-sm_103-safe helpers (no tcgen05: ptxas virtual target is compute_103)
// ===========================================================================
__device__ __forceinline__ uint32_t smem_u32(const void* p) {
    uint32_t a;
    asm("{ .reg .u64 t; cvta.to.shared.u64 t, %1; cvt.u32.u64 %0, t; }" : "=r"(a) : "l"(p));
    return a;
}
__device__ __forceinline__ void ldsm_x4(uint32_t* r, uint32_t addr) {
    asm volatile("ldmatrix.sync.aligned.m8n8.x4.shared.b16 {%0,%1,%2,%3}, [%4];"
                 : "=r"(r[0]), "=r"(r[1]), "=r"(r[2]), "=r"(r[3]) : "r"(addr));
}
__device__ __forceinline__ void ldsm_x4_t(uint32_t* r, uint32_t addr) {
    asm volatile("ldmatrix.sync.aligned.m8n8.x4.trans.shared.b16 {%0,%1,%2,%3}, [%4];"
                 : "=r"(r[0]), "=r"(r[1]), "=r"(r[2]), "=r"(r[3]) : "r"(addr));
}
__device__ __forceinline__ void mma_bf(float* d, const uint32_t* a, uint32_t b0, uint32_t b1) {
    asm volatile(
        "mma.sync.aligned.m16n8k16.row.col.f32.bf16.bf16.f32 "
        "{%0,%1,%2,%3}, {%4,%5,%6,%7}, {%8,%9}, {%0,%1,%2,%3};"
        : "+f"(d[0]), "+f"(d[1]), "+f"(d[2]), "+f"(d[3])
        : "r"(a[0]), "r"(a[1]), "r"(a[2]), "r"(a[3]), "r"(b0), "r"(b1));
}
__device__ __forceinline__ void mma_f16(float* d, const uint32_t* a, uint32_t b0, uint32_t b1) {
    asm volatile(
        "mma.sync.aligned.m16n8k16.row.col.f32.f16.f16.f32 "
        "{%0,%1,%2,%3}, {%4,%5,%6,%7}, {%8,%9}, {%0,%1,%2,%3};"
        : "+f"(d[0]), "+f"(d[1]), "+f"(d[2]), "+f"(d[3])
        : "r"(a[0]), "r"(a[1]), "r"(a[2]), "r"(a[3]), "r"(b0), "r"(b1));
}
__device__ __forceinline__ uint32_t pack_f16x2(float lo, float hi) {
    uint32_t d;
    asm("cvt.rn.f16x2.f32 %0, %1, %2;" : "=r"(d) : "f"(hi), "f"(lo));
    return d;
}
__device__ __forceinline__ void cpa16(uint32_t dst, const void* src) {
    asm volatile("cp.async.cg.shared.global [%0], [%1], 16;" :: "r"(dst), "l"(src) : "memory");
}

// ===========================================================================
// fp32 -> bf16 hi/lo splits
// ===========================================================================
__global__ __launch_bounds__(256) void split_f32(
    const float4* __restrict__ x, uint2* __restrict__ hi, uint2* __restrict__ lo, int n4)
{
    int i = blockIdx.x * blockDim.x + threadIdx.x;
    if (i >= n4) return;
    float4 v = x[i];
    float vv[4] = {v.x, v.y, v.z, v.w};
    __nv_bfloat16 h[4], l[4];
#pragma unroll
    for (int j = 0; j < 4; j++) {
        h[j] = __float2bfloat16(vv[j]);
        l[j] = __float2bfloat16(vv[j] - __bfloat162float(h[j]));
    }
    hi[i] = *(uint2*)h;
    lo[i] = *(uint2*)l;
}

__global__ __launch_bounds__(256) void split_w(
    const float4* __restrict__ w0, const float4* __restrict__ w1,
    const float4* __restrict__ w2, const float4* __restrict__ w3,
    uint2* __restrict__ hi, uint2* __restrict__ lo)
{
    const int z = blockIdx.y;
    const float4* src = (z == 0) ? w0 : (z == 1) ? w1 : (z == 2) ? w2 : w3;
    int i = blockIdx.x * blockDim.x + threadIdx.x;
    if (i >= WELE / 4) return;
    float4 v = src[i];
    float vv[4] = {v.x, v.y, v.z, v.w};
    __nv_bfloat16 h[4], l[4];
#pragma unroll
    for (int j = 0; j < 4; j++) {
        h[j] = __float2bfloat16(vv[j]);
        l[j] = __float2bfloat16(vv[j] - __bfloat162float(h[j]));
    }
    hi[(size_t)z * (WELE / 4) + i] = *(uint2*)h;
    lo[(size_t)z * (WELE / 4) + i] = *(uint2*)l;
}

// ===========================================================================
// HMMA split-bf16 NT GEMM v2: block tile 128(m) x 64(n), K-chunk 64,
// 2-stage cp.async, ONE barrier per chunk, 2 CTAs/SM.
// 8 warps = 4m x 2n, warp tile 32x32.
// ===========================================================================
#define GTA (128 * AST * 2)          // A array bytes/stage (18432)
#define GTB (64 * AST * 2)           // B array bytes/stage (9216)
#define GSTB (2 * GTA + 2 * GTB)     // stage stride (55296)

__global__ __launch_bounds__(256, 2) void gemm_mma(
    const __nv_bfloat16* __restrict__ Ahi, const __nv_bfloat16* __restrict__ Alo,
    const __nv_bfloat16* __restrict__ Whi, const __nv_bfloat16* __restrict__ Wlo,
    const float* __restrict__ bias, float* __restrict__ Cf,
    __nv_bfloat16* __restrict__ Chi, __nv_bfloat16* __restrict__ Clo,
    __half* __restrict__ Cf16, int wbase)
{
    extern __shared__ __align__(16) __nv_bfloat16 smb[];
    const uint32_t sb = smem_u32(smb);

    const int tid = threadIdx.x, wid = tid >> 5, lane = tid & 31;
    const int wm = (wid >> 1) * 32, wn = (wid & 1) * 32;
    const int m0 = blockIdx.y * 128, n0 = blockIdx.x * 64;
    const int z = blockIdx.z;

    const __nv_bfloat16* gAh = Ahi + (size_t)m0 * 768;
    const __nv_bfloat16* gAl = Alo + (size_t)m0 * 768;
    const __nv_bfloat16* gBh = Whi + (size_t)(wbase + z) * WELE + (size_t)n0 * 768;
    const __nv_bfloat16* gBl = Wlo + (size_t)(wbase + z) * WELE + (size_t)n0 * 768;

    float acc[2][4][4];
#pragma unroll
    for (int i = 0; i < 2; i++)
#pragma unroll
        for (int j = 0; j < 4; j++)
#pragma unroll
            for (int k = 0; k < 4; k++) acc[i][j][k] = 0.f;

#define GSTAGE(buf, c_)                                                        \
    {                                                                          \
        uint32_t base_ = sb + (buf) * GSTB;                                    \
        const int k0_ = (c_) * 64;                                             \
        _Pragma("unroll")                                                      \
        for (int it = 0; it < 4; it++) {                                       \
            int idx = it * 256 + tid;                                          \
            int row = idx >> 3, cc = idx & 7;                                  \
            uint32_t off = (uint32_t)(row * AST + cc * 8) * 2;                 \
            size_t go = (size_t)row * 768 + k0_ + cc * 8;                      \
            cpa16(base_ + off,       gAh + go);                                \
            cpa16(base_ + GTA + off, gAl + go);                                \
        }                                                                      \
        _Pragma("unroll")                                                      \
        for (int it = 0; it < 2; it++) {                                       \
            int idx = it * 256 + tid;                                          \
            int row = idx >> 3, cc = idx & 7;                                  \
            uint32_t off = (uint32_t)(row * AST + cc * 8) * 2;                 \
            size_t go = (size_t)row * 768 + k0_ + cc * 8;                      \
            cpa16(base_ + 2 * GTA + off,       gBh + go);                      \
            cpa16(base_ + 2 * GTA + GTB + off, gBl + go);                      \
        }                                                                      \
        asm volatile("cp.async.commit_group;" ::: "memory");                   \
    }

    GSTAGE(0, 0);

    const int lrow = lane & 15, lcol8 = (lane >> 4) * 8;
    const uint32_t offA = (uint32_t)((wm + lrow) * AST + lcol8) * 2;
    const uint32_t offB = (uint32_t)((wn + lrow) * AST + lcol8) * 2;

    for (int c = 0; c < 12; c++) {
        asm volatile("cp.async.wait_group 0;" ::: "memory");
        __syncthreads();
        if (c + 1 < 12) GSTAGE((c + 1) & 1, c + 1);   // writes buf read at c-1: safe after sync
        uint32_t base = sb + (c & 1) * GSTB;
        uint32_t aAh = base + offA, aAl = base + GTA + offA;
        uint32_t aBh = base + 2 * GTA + offB, aBl = base + 2 * GTA + GTB + offB;
#pragma unroll
        for (int kk = 0; kk < 4; kk++) {
            const uint32_t koff = kk * 32;   // 16 elements * 2B
            uint32_t ah[2][4], al[2][4], bh[2][4], bl[2][4];
#pragma unroll
            for (int mf = 0; mf < 2; mf++) {
                ldsm_x4(ah[mf], aAh + mf * 16 * AST * 2 + koff);
                ldsm_x4(al[mf], aAl + mf * 16 * AST * 2 + koff);
            }
#pragma unroll
            for (int nq = 0; nq < 2; nq++) {
                ldsm_x4(bh[nq], aBh + nq * 16 * AST * 2 + koff);
                ldsm_x4(bl[nq], aBl + nq * 16 * AST * 2 + koff);
            }
#pragma unroll
            for (int mf = 0; mf < 2; mf++) {
#pragma unroll
                for (int nq = 0; nq < 2; nq++) {
                    float* a0 = acc[mf][nq * 2 + 0];
                    float* a1 = acc[mf][nq * 2 + 1];
                    mma_bf(a0, ah[mf], bh[nq][0], bh[nq][2]);
                    mma_bf(a1, ah[mf], bh[nq][1], bh[nq][3]);
                    mma_bf(a0, al[mf], bh[nq][0], bh[nq][2]);
                    mma_bf(a1, al[mf], bh[nq][1], bh[nq][3]);
                    mma_bf(a0, ah[mf], bl[nq][0], bl[nq][2]);
                    mma_bf(a1, ah[mf], bl[nq][1], bl[nq][3]);
                }
            }
        }
    }

#pragma unroll
    for (int mf = 0; mf < 2; mf++) {
#pragma unroll
        for (int nf = 0; nf < 4; nf++) {
            int row = m0 + wm + mf * 16 + (lane >> 2);
            int col = n0 + wn + nf * 8 + (lane & 3) * 2;
            float v0 = acc[mf][nf][0], v1 = acc[mf][nf][1];
            float v2 = acc[mf][nf][2], v3 = acc[mf][nf][3];
            if (Cf) {
                float b0 = bias[col], b1 = bias[col + 1];
                *(float2*)(Cf + (size_t)row * 768 + col) = make_float2(v0 + b0, v1 + b1);
                *(float2*)(Cf + (size_t)(row + 8) * 768 + col) = make_float2(v2 + b0, v3 + b1);
            } else if (z == 2) {
                __half2 h0 = __floats2half2_rn(v0, v1);
                __half2 h1 = __floats2half2_rn(v2, v3);
                *(uint32_t*)(Cf16 + (size_t)row * 768 + col) = *(uint32_t*)&h0;
                *(uint32_t*)(Cf16 + (size_t)(row + 8) * 768 + col) = *(uint32_t*)&h1;
            } else {
                __nv_bfloat16* ch = Chi + (size_t)z * TOTE;
                __nv_bfloat16* cl = Clo + (size_t)z * TOTE;
                __nv_bfloat16 h0 = __float2bfloat16(v0), h1 = __float2bfloat16(v1);
                __nv_bfloat16 h2 = __float2bfloat16(v2), h3 = __float2bfloat16(v3);
                __nv_bfloat162 ph0 = {h0, h1}, ph1 = {h2, h3};
                __nv_bfloat162 pl0 = {__float2bfloat16(v0 - __bfloat162float(h0)),
                                      __float2bfloat16(v1 - __bfloat162float(h1))};
                __nv_bfloat162 pl1 = {__float2bfloat16(v2 - __bfloat162float(h2)),
                                      __float2bfloat16(v3 - __bfloat162float(h3))};
                *(uint32_t*)(ch + (size_t)row * 768 + col) = *(uint32_t*)&ph0;
                *(uint32_t*)(ch + (size_t)(row + 8) * 768 + col) = *(uint32_t*)&ph1;
                *(uint32_t*)(cl + (size_t)row * 768 + col) = *(uint32_t*)&pl0;
                *(uint32_t*)(cl + (size_t)(row + 8) * 768 + col) = *(uint32_t*)&pl1;
            }
        }
    }
}

// ===========================================================================
// HMMA fused biased flash attention, v4: key tile 32, 3-stage cp.async
// pipeline (K hi/lo + V + W), ONE barrier per tile, 2 CTAs/SM.
// ===========================================================================
#define KT 32
#define KVB (KT * AST * 2)            // 4608 B per K/V array per stage
#define WB  (128 * WSTW * 4)          // 18432 B W tile per stage
#define STB (3 * KVB + WB)            // stage stride 32256 B

__global__ __launch_bounds__(256, 2) void attn_mma(
    const __nv_bfloat16* __restrict__ qkh, const __nv_bfloat16* __restrict__ qkl,
    const __half* __restrict__ vf, const float* __restrict__ W,
    __nv_bfloat16* __restrict__ ohi, __nv_bfloat16* __restrict__ olo)
{
    extern __shared__ __align__(16) char smn[];
    const uint32_t sb = smem_u32(smn);

    const int tid = threadIdx.x, wp = tid >> 5, lane = tid & 31;
    const int n0 = blockIdx.x * 128, h = blockIdx.y, b = blockIdx.z;

    const __nv_bfloat16* qh = qkh + ((size_t)(b * 1024 + n0)) * 768 + h * 64;
    const __nv_bfloat16* ql = qkl + ((size_t)(b * 1024 + n0)) * 768 + h * 64;
    const __nv_bfloat16* kh = qkh + (size_t)TOTE + (size_t)b * 1024 * 768 + h * 64;
    const __nv_bfloat16* kl = qkl + (size_t)TOTE + (size_t)b * 1024 * 768 + h * 64;
    const __half* vg = vf + (size_t)b * 1024 * 768 + h * 64;
    const float* wg = W + ((size_t)(b * 12 + h) * 1024 + n0) * 1024;

    // --- Stage Q (128x64) hi/lo through smem (pre-pipeline), frags to regs ---
    {
        __nv_bfloat16* tQh = (__nv_bfloat16*)smn;
        __nv_bfloat16* tQl = tQh + 128 * AST;
#pragma unroll
        for (int it = 0; it < 4; it++) {
            int idx = it * 256 + tid;
            int row = idx >> 3, cc = idx & 7;
            *(uint4*)(tQh + row * AST + cc * 8) = *(const uint4*)(qh + (size_t)row * 768 + cc * 8);
            *(uint4*)(tQl + row * AST + cc * 8) = *(const uint4*)(ql + (size_t)row * 768 + cc * 8);
        }
    }
    __syncthreads();
    uint32_t qfh[4][4], qfl[4][4];
    {
        uint32_t off = (uint32_t)((wp * 16 + (lane & 15)) * AST + (lane >> 4) * 8) * 2;
#pragma unroll
        for (int ks = 0; ks < 4; ks++) {
            ldsm_x4(qfh[ks], sb + off + ks * 32);
            ldsm_x4(qfl[ks], sb + 128 * AST * 2 + off + ks * 32);
        }
    }
    __syncthreads();

    float oacc[8][4];
#pragma unroll
    for (int d = 0; d < 8; d++)
#pragma unroll
        for (int j = 0; j < 4; j++) oacc[d][j] = 0.f;
    float m0r = -INFINITY, m1r = -INFINITY, l0r = 0.f, l1r = 0.f;

#define ASTAGE(buf, t_)                                                        \
    {                                                                          \
        uint32_t base_ = sb + (buf) * STB;                                     \
        const int s0_ = (t_) * KT;                                             \
        {                                                                      \
            int row = tid >> 3, cc = tid & 7;                                  \
            uint32_t doff = (uint32_t)(row * AST + cc * 8) * 2;                \
            size_t go = (size_t)(s0_ + row) * 768 + cc * 8;                    \
            cpa16(base_ + doff,           kh + go);                            \
            cpa16(base_ + KVB + doff,     kl + go);                            \
            cpa16(base_ + 2 * KVB + doff, vg + go);                            \
        }                                                                      \
        _Pragma("unroll")                                                      \
        for (int it = 0; it < 4; it++) {                                       \
            int idx = it * 256 + tid;                                          \
            int row = idx >> 3, cc = idx & 7;                                  \
            cpa16(base_ + 3 * KVB + (uint32_t)(row * WSTW + cc * 4) * 4,       \
                  wg + (size_t)row * 1024 + s0_ + cc * 4);                     \
        }                                                                      \
        asm volatile("cp.async.commit_group;" ::: "memory");                   \
    }

    ASTAGE(0, 0); ASTAGE(1, 1);

    const uint32_t foff = (uint32_t)(((lane & 15) * AST) + (lane >> 4) * 8) * 2;
    const int c0 = (lane & 3) * 2;
    const uint32_t woff = (uint32_t)((wp * 16 + (lane >> 2)) * WSTW + c0) * 4;

    for (int t = 0; t < 32; t++) {
        if (t + 2 < 32) {
            asm volatile("cp.async.wait_group 1;" ::: "memory");
        } else {
            asm volatile("cp.async.wait_group 0;" ::: "memory");
        }
        __syncthreads();
        if (t + 2 < 32) ASTAGE((t + 2) % 3, t + 2);   // writes stage read at t-1: safe after sync
        uint32_t base = sb + (t % 3) * STB;
        uint32_t kbh = base + foff, kbl = base + KVB + foff;
        uint32_t vbb = base + 2 * KVB + foff;
        uint32_t wb0 = base + 3 * KVB + woff;

        // ---- S = Q K^T (3-term split-bf16), 32 keys ----
        float sc[4][4];
#pragma unroll
        for (int nf = 0; nf < 4; nf++)
#pragma unroll
            for (int j = 0; j < 4; j++) sc[nf][j] = 0.f;
#pragma unroll
        for (int nf2 = 0; nf2 < 2; nf2++) {
#pragma unroll
            for (int ks = 0; ks < 4; ks++) {
                uint32_t off = (uint32_t)(nf2 * 16 * AST + ks * 16) * 2;
                uint32_t fh[4], fl[4];
                ldsm_x4(fh, kbh + off);
                ldsm_x4(fl, kbl + off);
                mma_bf(sc[2 * nf2],     qfh[ks], fh[0], fh[2]);
                mma_bf(sc[2 * nf2 + 1], qfh[ks], fh[1], fh[3]);
                mma_bf(sc[2 * nf2],     qfl[ks], fh[0], fh[2]);
                mma_bf(sc[2 * nf2 + 1], qfl[ks], fh[1], fh[3]);
                mma_bf(sc[2 * nf2],     qfh[ks], fl[0], fl[2]);
                mma_bf(sc[2 * nf2 + 1], qfh[ks], fl[1], fl[3]);
            }
        }

        // ---- bias (from smem) + online softmax ----
        float nm0 = m0r, nm1 = m1r;
#pragma unroll
        for (int nf = 0; nf < 4; nf++) {
            float2 w0, w1;
            asm volatile("ld.shared.v2.f32 {%0,%1}, [%2];"
                         : "=f"(w0.x), "=f"(w0.y) : "r"(wb0 + nf * 32));
            asm volatile("ld.shared.v2.f32 {%0,%1}, [%2];"
                         : "=f"(w1.x), "=f"(w1.y) : "r"(wb0 + 8 * WSTW * 4 + nf * 32));
            sc[nf][0] = fmaf(sc[nf][0], 0.125f, w0.x);
            sc[nf][1] = fmaf(sc[nf][1], 0.125f, w0.y);
            sc[nf][2] = fmaf(sc[nf][2], 0.125f, w1.x);
            sc[nf][3] = fmaf(sc[nf][3], 0.125f, w1.y);
            nm0 = fmaxf(nm0, fmaxf(sc[nf][0], sc[nf][1]));
            nm1 = fmaxf(nm1, fmaxf(sc[nf][2], sc[nf][3]));
        }
        nm0 = fmaxf(nm0, __shfl_xor_sync(0xffffffffu, nm0, 1));
        nm0 = fmaxf(nm0, __shfl_xor_sync(0xffffffffu, nm0, 2));
        nm1 = fmaxf(nm1, __shfl_xor_sync(0xffffffffu, nm1, 1));
        nm1 = fmaxf(nm1, __shfl_xor_sync(0xffffffffu, nm1, 2));
        float corr0 = __expf(m0r - nm0), corr1 = __expf(m1r - nm1);
        m0r = nm0; m1r = nm1;
        float rs0 = 0.f, rs1 = 0.f;
#pragma unroll
        for (int nf = 0; nf < 4; nf++) {
            sc[nf][0] = __expf(sc[nf][0] - nm0);
            sc[nf][1] = __expf(sc[nf][1] - nm0);
            sc[nf][2] = __expf(sc[nf][2] - nm1);
            sc[nf][3] = __expf(sc[nf][3] - nm1);
            rs0 += sc[nf][0] + sc[nf][1];
            rs1 += sc[nf][2] + sc[nf][3];
        }
        l0r = l0r * corr0 + rs0;
        l1r = l1r * corr1 + rs1;
#pragma unroll
        for (int d = 0; d < 8; d++) {
            oacc[d][0] *= corr0; oacc[d][1] *= corr0;
            oacc[d][2] *= corr1; oacc[d][3] *= corr1;
        }

        // ---- out += P V (fp16, P from registers) ----
#pragma unroll
        for (int kc = 0; kc < 2; kc++) {
            uint32_t pa[4];
            pa[0] = pack_f16x2(sc[2 * kc][0], sc[2 * kc][1]);
            pa[1] = pack_f16x2(sc[2 * kc][2], sc[2 * kc][3]);
            pa[2] = pack_f16x2(sc[2 * kc + 1][0], sc[2 * kc + 1][1]);
            pa[3] = pack_f16x2(sc[2 * kc + 1][2], sc[2 * kc + 1][3]);
#pragma unroll
            for (int dp = 0; dp < 4; dp++) {
                uint32_t vf4[4];
                ldsm_x4_t(vf4, vbb + (uint32_t)(kc * 16 * AST + dp * 16) * 2);
                mma_f16(oacc[2 * dp],     pa, vf4[0], vf4[1]);
                mma_f16(oacc[2 * dp + 1], pa, vf4[2], vf4[3]);
            }
        }
    }

    // ---- normalize + write bf16 hi/lo (att layout [4096, 768]) ----
    l0r += __shfl_xor_sync(0xffffffffu, l0r, 1);
    l0r += __shfl_xor_sync(0xffffffffu, l0r, 2);
    l1r += __shfl_xor_sync(0xffffffffu, l1r, 1);
    l1r += __shfl_xor_sync(0xffffffffu, l1r, 2);
    float i0 = 1.f / l0r, i1 = 1.f / l1r;
    int row = b * 1024 + n0 + wp * 16 + (lane >> 2);
    int colb = h * 64 + c0;
#pragma unroll
    for (int d = 0; d < 8; d++) {
        float v0 = oacc[d][0] * i0, v1 = oacc[d][1] * i0;
        float v2 = oacc[d][2] * i1, v3 = oacc[d][3] * i1;
        __nv_bfloat16 h0 = __float2bfloat16(v0), h1 = __float2bfloat16(v1);
        __nv_bfloat16 h2 = __float2bfloat16(v2), h3 = __float2bfloat16(v3);
        __nv_bfloat162 ph0 = {h0, h1}, ph1 = {h2, h3};
        __nv_bfloat162 pl0 = {__float2bfloat16(v0 - __bfloat162float(h0)),
                              __float2bfloat16(v1 - __bfloat162float(h1))};
        __nv_bfloat162 pl1 = {__float2bfloat16(v2 - __bfloat162float(h2)),
                              __float2bfloat16(v3 - __bfloat162float(h3))};
        *(uint32_t*)(ohi + (size_t)row * 768 + colb + d * 8) = *(uint32_t*)&ph0;
        *(uint32_t*)(ohi + (size_t)(row + 8) * 768 + colb + d * 8) = *(uint32_t*)&ph1;
        *(uint32_t*)(olo + (size_t)row * 768 + colb + d * 8) = *(uint32_t*)&pl0;
        *(uint32_t*)(olo + (size_t)(row + 8) * 768 + colb + d * 8) = *(uint32_t*)&pl1;
    }
}

// ===========================================================================
// Launch
// ===========================================================================
extern "C" void kernel_launch(void* const* d_in, const int* in_sizes, int n_in,
                              void* d_out, int out_size)
{
    const float* query = (const float*)d_in[0];
    const float* attw  = (const float*)d_in[1];
    const float* Wq    = (const float*)d_in[2];
    const float* Wk    = (const float*)d_in[3];
    const float* Wv    = (const float*)d_in[4];
    const float* Wo    = (const float*)d_in[5];
    const float* bo    = (const float*)d_in[6];
    float* out = (float*)d_out;

    __nv_bfloat16 *ahi, *alo, *whi, *wlo, *qkh, *qkl;
    __half* vfp;
    cudaGetSymbolAddress((void**)&ahi, g_ahi);
    cudaGetSymbolAddress((void**)&alo, g_alo);
    cudaGetSymbolAddress((void**)&whi, g_whi);
    cudaGetSymbolAddress((void**)&wlo, g_wlo);
    cudaGetSymbolAddress((void**)&qkh, g_qkh);
    cudaGetSymbolAddress((void**)&qkl, g_qkl);
    cudaGetSymbolAddress((void**)&vfp, g_vf);

    const int gemm_smem = 2 * GSTB;                // 110592 (2 CTAs/SM)
    cudaFuncSetAttribute(gemm_mma, cudaFuncAttributeMaxDynamicSharedMemorySize, gemm_smem);
    const int attn_smem = 3 * STB;                 // 96768 (2 CTAs/SM)
    cudaFuncSetAttribute(attn_mma, cudaFuncAttributeMaxDynamicSharedMemorySize, attn_smem);

    // 1) Split query + all four weights
    split_f32<<<TOTE / 4 / 256, 256>>>((const float4*)query, (uint2*)ahi, (uint2*)alo, TOTE / 4);
    split_w<<<dim3(WELE / 4 / 256, 4), 256>>>((const float4*)Wq, (const float4*)Wk,
                                              (const float4*)Wv, (const float4*)Wo,
                                              (uint2*)whi, (uint2*)wlo);

    // 2) QKV: z<2 -> Q/K bf16 hi/lo, z==2 -> V fp16
    gemm_mma<<<dim3(12, 32, 3), 256, gemm_smem>>>(ahi, alo, whi, wlo,
                                                  nullptr, nullptr, qkh, qkl, vfp, 0);

    // 3) Fused biased attention; att hi/lo -> ahi/alo
    attn_mma<<<dim3(8, 12, 4), 256, attn_smem>>>(qkh, qkl, vfp, attw, ahi, alo);

    // 4) Output projection (fp32 + bias)
    gemm_mma<<<dim3(12, 32, 1), 256, gemm_smem>>>(ahi, alo, whi, wlo,
                                                  bo, out, nullptr, nullptr, nullptr, 3);
}